// round 4
// baseline (speedup 1.0000x reference)
#include <cuda_runtime.h>
#include <cstdint>
#include <cstddef>

// ---------------------------------------------------------------------------
// WeightedScaledDotProductAttention (B=8, N=2048, D=1024)
//   q_out = q @ W1^T + b1
//   attn  = q_out @ q_out^T        (per batch)
//   dinv  = rsqrt(max(rowsum(attn), 1))
//   out   = dinv[:,None] * attn * dinv[None,:]
// returns (out, attn)  -> d_out = [out | attn]
// BOTH GEMMs: split-tf32 (hi/lo, 3 MMAs) -> fp32-accurate results.
// (plain tf32 GEMM2 measured rel_err 1.7e-3 > 1e-3 gate; split fixes it)
// ---------------------------------------------------------------------------

#define BM 128
#define BN 128
#define BK 32
#define SSTRIDE 36   // BK + 4 pad: bank = (4*m + k) mod 32, conflict-free frags

static const int cB = 8, cN = 2048, cD = 1024;

// scratch (static device globals: no runtime allocation)
__device__ float g_qout[(size_t)8 * 2048 * 1024];          // 64 MB
__device__ float g_attn[(size_t)8 * 2048 * 2048];          // 128 MB fallback
__device__ float g_rowsum[8 * 2048];

__device__ __forceinline__ uint32_t f2tf32(float f) {
    uint32_t r;
    asm("cvt.rna.tf32.f32 %0, %1;" : "=r"(r) : "f"(f));   // .rna: unbiased rounding
    return r;
}

__device__ __forceinline__ void mma_tf32(float c[4], const uint32_t a[4], const uint32_t b[2]) {
    asm volatile(
        "mma.sync.aligned.m16n8k8.row.col.f32.tf32.tf32.f32 "
        "{%0,%1,%2,%3}, {%4,%5,%6,%7}, {%8,%9}, {%0,%1,%2,%3};"
        : "+f"(c[0]), "+f"(c[1]), "+f"(c[2]), "+f"(c[3])
        : "r"(a[0]), "r"(a[1]), "r"(a[2]), "r"(a[3]), "r"(b[0]), "r"(b[1]));
}

__device__ __forceinline__ void cpasync16(float* smem_dst, const float* gmem_src) {
    uint32_t s = (uint32_t)__cvta_generic_to_shared(smem_dst);
    asm volatile("cp.async.cg.shared.global [%0], [%1], 16;" :: "r"(s), "l"(gmem_src));
}

// split x into hi (tf32) + lo (tf32 of residual): effective ~fp32 operand
__device__ __forceinline__ void split_tf32(float x, uint32_t& hi, uint32_t& lo) {
    hi = f2tf32(x);
    lo = f2tf32(x - __uint_as_float(hi));
}

// C[M,Ndim] = A[M,K] * B[Ndim,K]^T  (A row-major lda=K, B row-major ldb=K)
template <bool ROWSUM, bool BIAS, bool SPLIT>
__global__ __launch_bounds__(256)
void gemm_nt(const float* __restrict__ Ag, const float* __restrict__ Bg,
             const float* __restrict__ bias, float* __restrict__ Cg,
             float* __restrict__ rowsumg,
             int M, int Ndim, int K,
             size_t sA, size_t sB, size_t sC)
{
    extern __shared__ float smem[];
    float* As = smem;                          // [2][BM][SSTRIDE]
    float* Bs = smem + 2 * BM * SSTRIDE;       // [2][BN][SSTRIDE]

    const int z = blockIdx.z;
    const float* A = Ag + (size_t)z * sA;
    const float* B = Bg + (size_t)z * sB;
    float* C = Cg + (size_t)z * sC;
    float* rowsum = ROWSUM ? (rowsumg + (size_t)z * M) : nullptr;

    const int bm = blockIdx.y * BM;
    const int bn = blockIdx.x * BN;

    const int tid  = threadIdx.x;
    const int lane = tid & 31;
    const int warp = tid >> 5;
    const int g = lane >> 2;            // 0..7
    const int t = lane & 3;             // 0..3
    const int wm0 = (warp >> 2) * 64;   // warp tile 64x32; warp grid 2x4
    const int wn0 = (warp & 3) * 32;

    float acc[4][4][4];
    #pragma unroll
    for (int i = 0; i < 4; i++)
        #pragma unroll
        for (int j = 0; j < 4; j++)
            #pragma unroll
            for (int r = 0; r < 4; r++) acc[i][j][r] = 0.f;

    const int KT = K / BK;

    auto load_tile = [&](int kt, int buf) {
        const float* Asrc = A + (size_t)bm * K + kt * BK;
        const float* Bsrc = B + (size_t)bn * K + kt * BK;
        float* Ad = As + buf * BM * SSTRIDE;
        float* Bd = Bs + buf * BN * SSTRIDE;
        #pragma unroll
        for (int i = 0; i < 4; i++) {
            int idx = tid + i * 256;            // 0..1023
            int row = idx >> 3;                 // 0..127
            int c4  = (idx & 7) * 4;            // 0,4,..,28
            cpasync16(Ad + row * SSTRIDE + c4, Asrc + (size_t)row * K + c4);
            cpasync16(Bd + row * SSTRIDE + c4, Bsrc + (size_t)row * K + c4);
        }
        asm volatile("cp.async.commit_group;");
    };

    load_tile(0, 0);
    asm volatile("cp.async.wait_group 0;");
    __syncthreads();

    int buf = 0;
    for (int kt = 0; kt < KT; kt++) {
        if (kt + 1 < KT) load_tile(kt + 1, buf ^ 1);
        const float* Ab = As + buf * BM * SSTRIDE;
        const float* Bb = Bs + buf * BN * SSTRIDE;

        #pragma unroll
        for (int ks = 0; ks < BK / 8; ks++) {
            const int k0 = ks * 8;
            uint32_t ah[4][4], bh[4][2];
            uint32_t al[4][4], bl[4][2];
            #pragma unroll
            for (int mt = 0; mt < 4; mt++) {
                int r = wm0 + mt * 16 + g;
                float x0 = Ab[r * SSTRIDE + k0 + t];
                float x1 = Ab[(r + 8) * SSTRIDE + k0 + t];
                float x2 = Ab[r * SSTRIDE + k0 + t + 4];
                float x3 = Ab[(r + 8) * SSTRIDE + k0 + t + 4];
                if (SPLIT) {
                    split_tf32(x0, ah[mt][0], al[mt][0]);
                    split_tf32(x1, ah[mt][1], al[mt][1]);
                    split_tf32(x2, ah[mt][2], al[mt][2]);
                    split_tf32(x3, ah[mt][3], al[mt][3]);
                } else {
                    ah[mt][0] = f2tf32(x0); ah[mt][1] = f2tf32(x1);
                    ah[mt][2] = f2tf32(x2); ah[mt][3] = f2tf32(x3);
                }
            }
            #pragma unroll
            for (int nt = 0; nt < 4; nt++) {
                int c = wn0 + nt * 8 + g;
                float y0 = Bb[c * SSTRIDE + k0 + t];
                float y1 = Bb[c * SSTRIDE + k0 + t + 4];
                if (SPLIT) {
                    split_tf32(y0, bh[nt][0], bl[nt][0]);
                    split_tf32(y1, bh[nt][1], bl[nt][1]);
                } else {
                    bh[nt][0] = f2tf32(y0); bh[nt][1] = f2tf32(y1);
                }
            }
            #pragma unroll
            for (int mt = 0; mt < 4; mt++)
                #pragma unroll
                for (int nt = 0; nt < 4; nt++) {
                    if (SPLIT) {
                        // (ah+al)*(bh+bl) ~= ah*bh + ah*bl + al*bh  (lo*lo ~2^-24, dropped)
                        mma_tf32(acc[mt][nt], ah[mt], bl[nt]);
                        mma_tf32(acc[mt][nt], al[mt], bh[nt]);
                    }
                    mma_tf32(acc[mt][nt], ah[mt], bh[nt]);
                }
        }
        if (kt + 1 < KT) asm volatile("cp.async.wait_group 0;");
        __syncthreads();
        buf ^= 1;
    }

    // epilogue: bias add, coalesced float2 stores, fused row-sum reduction
    #pragma unroll
    for (int mt = 0; mt < 4; mt++) {
        const int r0 = bm + wm0 + mt * 16 + g;    // absolute in-batch row
        float rs0 = 0.f, rs1 = 0.f;
        #pragma unroll
        for (int nt = 0; nt < 4; nt++) {
            const int c = bn + wn0 + nt * 8 + 2 * t;
            float c0 = acc[mt][nt][0], c1 = acc[mt][nt][1];
            float c2 = acc[mt][nt][2], c3 = acc[mt][nt][3];
            if (BIAS) {
                float bb0 = bias[c], bb1 = bias[c + 1];
                c0 += bb0; c1 += bb1; c2 += bb0; c3 += bb1;
            }
            *(float2*)(C + (size_t)r0 * Ndim + c)       = make_float2(c0, c1);
            *(float2*)(C + (size_t)(r0 + 8) * Ndim + c) = make_float2(c2, c3);
            if (ROWSUM) { rs0 += c0 + c1; rs1 += c2 + c3; }
        }
        if (ROWSUM) {
            rs0 += __shfl_xor_sync(0xffffffffu, rs0, 1);
            rs0 += __shfl_xor_sync(0xffffffffu, rs0, 2);
            rs1 += __shfl_xor_sync(0xffffffffu, rs1, 1);
            rs1 += __shfl_xor_sync(0xffffffffu, rs1, 2);
            if (t == 0) {
                atomicAdd(&rowsum[r0],     rs0);
                atomicAdd(&rowsum[r0 + 8], rs1);
            }
        }
    }
}

__global__ void zero_kernel(float* p, int n) {
    int i = blockIdx.x * blockDim.x + threadIdx.x;
    if (i < n) p[i] = 0.f;
}

__global__ void dinv_kernel(float* p, int n) {
    int i = blockIdx.x * blockDim.x + threadIdx.x;
    if (i < n) {
        float s = p[i];
        s = s > 1.f ? s : 1.f;
        p[i] = rsqrtf(s);
    }
}

// out[b,i,j] = dinv[b,i] * attn[b,i,j] * dinv[b,j]   (float4 vectorized)
__global__ void scale_kernel(const float* __restrict__ attn,
                             const float* __restrict__ dinv,
                             float* __restrict__ out,
                             int N, size_t total4)
{
    size_t i = (size_t)blockIdx.x * blockDim.x + threadIdx.x;
    if (i >= total4) return;
    size_t e = i * 4;
    size_t row = e / N;                 // b*N + i   (N is a power of two)
    int j = (int)(e - row * N);
    float4 a = ((const float4*)attn)[i];
    float di = dinv[row];
    const float4 dj = *(const float4*)(dinv + (row / N) * N + j);
    float4 o;
    o.x = a.x * di * dj.x;
    o.y = a.y * di * dj.y;
    o.z = a.z * di * dj.z;
    o.w = a.w * di * dj.w;
    ((float4*)out)[i] = o;
}

extern "C" void kernel_launch(void* const* d_in, const int* in_sizes, int n_in,
                              void* d_out, int out_size)
{
    const float* q  = (const float*)d_in[0];
    const float* W1 = (const float*)d_in[3];
    const float* b1 = (const float*)d_in[4];
    (void)in_sizes; (void)n_in;

    const int B = cB, N = cN, D = cD;
    const size_t BNN = (size_t)B * N * N;

    float *qout, *rowsum, *attn_scratch;
    cudaGetSymbolAddress((void**)&qout, g_qout);
    cudaGetSymbolAddress((void**)&rowsum, g_rowsum);
    cudaGetSymbolAddress((void**)&attn_scratch, g_attn);

    float* outp  = (float*)d_out;
    float* attnp = ((size_t)out_size >= 2 * BNN) ? (outp + BNN) : attn_scratch;

    const int smem = 2 * (BM * SSTRIDE + BN * SSTRIDE) * (int)sizeof(float); // 73728 B
    cudaFuncSetAttribute((const void*)gemm_nt<false, true, true>,
                         cudaFuncAttributeMaxDynamicSharedMemorySize, smem);
    cudaFuncSetAttribute((const void*)gemm_nt<true, false, true>,
                         cudaFuncAttributeMaxDynamicSharedMemorySize, smem);

    // 1) zero rowsum accumulators (inside capture: re-zeroed every replay)
    zero_kernel<<<(B * N + 255) / 256, 256>>>(rowsum, B * N);

    // 2) GEMM1 (split-tf32, fp32-accurate):
    //    q_out[16384,1024] = q[16384,1024] @ W1[1024,1024]^T + b1
    {
        dim3 grid(D / BN, (B * N) / BM, 1);
        gemm_nt<false, true, true><<<grid, 256, smem>>>(
            q, W1, b1, qout, nullptr,
            B * N, D, D, 0, 0, 0);
    }

    // 3) GEMM2 per batch (split-tf32): attn = q_out @ q_out^T, fused row sums
    {
        dim3 grid(N / BN, N / BM, B);
        gemm_nt<true, false, true><<<grid, 256, smem>>>(
            qout, qout, nullptr, attnp, rowsum,
            N, N, D,
            (size_t)N * D, (size_t)N * D, (size_t)N * N);
    }

    // 4) dinv = rsqrt(max(rowsum, 1))
    dinv_kernel<<<(B * N + 255) / 256, 256>>>(rowsum, B * N);

    // 5) out = dinv * attn * dinv
    {
        size_t total4 = BNN / 4;
        unsigned blocks = (unsigned)((total4 + 255) / 256);
        scale_kernel<<<blocks, 256>>>(attnp, rowsum, outp, N, total4);
    }
}

// round 6
// speedup vs baseline: 1.7419x; 1.7419x over previous
#include <cuda_runtime.h>
#include <cuda_bf16.h>
#include <cstdint>
#include <cstddef>

// ---------------------------------------------------------------------------
// WeightedScaledDotProductAttention (B=8, N=2048, D=1024)
//   q_out = q @ W1^T + b1 ; attn = q_out @ q_out^T (per batch)
//   dinv = rsqrt(max(rowsum(attn),1)); out = dinv*attn*dinv
// returns (out, attn) -> d_out = [out | attn]
//
// bf16 hi/lo split GEMMs (3x m16n8k16 MMA: hh + hl + lh), operands pre-split
// into bf16 planes so the GEMM inner loop is pure LDS + MMA (no cvt).
// Measured floor is fp32-accumulation noise ~8e-5; bf16-split adds ~2e-5.
// ---------------------------------------------------------------------------

#define BM 128
#define BN 128
#define BK 32
#define SROW 20                 // smem row stride in u32 (40 bf16): 20g+t mod 32 = perm
#define PLANE_U32 (BM * SROW)   // 2560 u32 per plane per buffer

static const int cB = 8, cN = 2048, cD = 1024;

// static device scratch (no runtime allocation allowed)
__device__ __nv_bfloat16 g_q_hi[(size_t)8 * 2048 * 1024];
__device__ __nv_bfloat16 g_q_lo[(size_t)8 * 2048 * 1024];
__device__ __nv_bfloat16 g_w_hi[(size_t)1024 * 1024];
__device__ __nv_bfloat16 g_w_lo[(size_t)1024 * 1024];
__device__ __nv_bfloat16 g_qo_hi[(size_t)8 * 2048 * 1024];
__device__ __nv_bfloat16 g_qo_lo[(size_t)8 * 2048 * 1024];
__device__ float g_attn[(size_t)8 * 2048 * 2048];   // fallback if out lacks attn
__device__ float g_rowsum[8 * 2048];

__device__ __forceinline__ uint32_t bits2(__nv_bfloat162 h) {
    uint32_t u; *reinterpret_cast<__nv_bfloat162*>(&u) = h; return u;
}

// pack (a,b) -> bf16x2 hi plane + bf16x2 lo (residual) plane; a in low half
__device__ __forceinline__ void split2(float a, float b, uint32_t& hi, uint32_t& lo) {
    __nv_bfloat162 h = __floats2bfloat162_rn(a, b);
    float ra = a - __bfloat162float(h.x);
    float rb = b - __bfloat162float(h.y);
    hi = bits2(h);
    lo = bits2(__floats2bfloat162_rn(ra, rb));
}

__device__ __forceinline__ void mma_bf16(float c[4], const uint32_t a[4], const uint32_t b[2]) {
    asm volatile(
        "mma.sync.aligned.m16n8k16.row.col.f32.bf16.bf16.f32 "
        "{%0,%1,%2,%3}, {%4,%5,%6,%7}, {%8,%9}, {%0,%1,%2,%3};"
        : "+f"(c[0]), "+f"(c[1]), "+f"(c[2]), "+f"(c[3])
        : "r"(a[0]), "r"(a[1]), "r"(a[2]), "r"(a[3]), "r"(b[0]), "r"(b[1]));
}

__device__ __forceinline__ void cpasync16(void* smem_dst, const void* gmem_src) {
    uint32_t s = (uint32_t)__cvta_generic_to_shared(smem_dst);
    asm volatile("cp.async.cg.shared.global [%0], [%1], 16;" :: "r"(s), "l"(gmem_src));
}

// elementwise f32 -> (hi, lo) bf16 planes, pair-vectorized
__global__ void split_planes_kernel(const float* __restrict__ x,
                                    __nv_bfloat16* __restrict__ hi,
                                    __nv_bfloat16* __restrict__ lo, size_t npairs)
{
    size_t i = (size_t)blockIdx.x * blockDim.x + threadIdx.x;
    if (i >= npairs) return;
    float2 v = ((const float2*)x)[i];
    uint32_t h, l;
    split2(v.x, v.y, h, l);
    ((uint32_t*)hi)[i] = h;
    ((uint32_t*)lo)[i] = l;
}

// C[M,Ndim] = (Ahi+Alo)[M,K] * (Bhi+Blo)[Ndim,K]^T via hh+hl+lh, fp32 acc.
// OUTSPLIT: emit bf16 hi/lo planes (+bias). Else: f32 C + fused rowsum atomics.
template <bool OUTSPLIT, bool BIAS, bool ROWSUM>
__global__ __launch_bounds__(256, 1)
void gemm_bf16split(const __nv_bfloat16* __restrict__ Ahi, const __nv_bfloat16* __restrict__ Alo,
                    const __nv_bfloat16* __restrict__ Bhi, const __nv_bfloat16* __restrict__ Blo,
                    const float* __restrict__ bias,
                    float* __restrict__ Cf,
                    __nv_bfloat16* __restrict__ Chi, __nv_bfloat16* __restrict__ Clo,
                    float* __restrict__ rowsumg,
                    int M, int Ndim, int K,
                    size_t sA, size_t sB, size_t sC)
{
    extern __shared__ uint32_t sm32[];   // [2 buf][4 planes][BM][SROW]

    const int z = blockIdx.z;
    const __nv_bfloat16* pA[2] = { Ahi + (size_t)z * sA, Alo + (size_t)z * sA };
    const __nv_bfloat16* pB[2] = { Bhi + (size_t)z * sB, Blo + (size_t)z * sB };
    float* C = OUTSPLIT ? nullptr : (Cf + (size_t)z * sC);
    float* rowsum = ROWSUM ? (rowsumg + (size_t)z * M) : nullptr;

    const int bm = blockIdx.y * BM;
    const int bn = blockIdx.x * BN;

    const int tid  = threadIdx.x;
    const int lane = tid & 31;
    const int warp = tid >> 5;
    const int g = lane >> 2;            // 0..7
    const int t = lane & 3;             // 0..3
    const int wm0 = (warp >> 2) * 64;   // warp grid 2x4, warp tile 64x32
    const int wn0 = (warp & 3) * 32;

    float acc[4][4][4];
    #pragma unroll
    for (int i = 0; i < 4; i++)
        #pragma unroll
        for (int j = 0; j < 4; j++)
            #pragma unroll
            for (int r = 0; r < 4; r++) acc[i][j][r] = 0.f;

    const int KT = K / BK;

    // 4 planes x 128 rows x 4 chunks(16B) = 2048 chunks; 8 per thread
    auto load_tile = [&](int kt, int buf) {
        uint32_t* base = sm32 + buf * 4 * PLANE_U32;
        #pragma unroll
        for (int p = 0; p < 4; p++) {
            const __nv_bfloat16* src = (p < 2) ? (pA[p] + (size_t)bm * K + kt * BK)
                                               : (pB[p - 2] + (size_t)bn * K + kt * BK);
            uint32_t* dst = base + p * PLANE_U32;
            #pragma unroll
            for (int j = 0; j < 2; j++) {
                int chunk = tid + j * 256;      // 0..511
                int r  = chunk >> 2;            // 0..127
                int ch = chunk & 3;             // 0..3
                cpasync16(dst + r * SROW + ch * 4, src + (size_t)r * K + ch * 8);
            }
        }
        asm volatile("cp.async.commit_group;");
    };

    load_tile(0, 0);
    asm volatile("cp.async.wait_group 0;");
    __syncthreads();

    int buf = 0;
    for (int kt = 0; kt < KT; kt++) {
        if (kt + 1 < KT) load_tile(kt + 1, buf ^ 1);
        const uint32_t* Ah = sm32 + (buf * 4 + 0) * PLANE_U32;
        const uint32_t* Al = sm32 + (buf * 4 + 1) * PLANE_U32;
        const uint32_t* Bh = sm32 + (buf * 4 + 2) * PLANE_U32;
        const uint32_t* Bl = sm32 + (buf * 4 + 3) * PLANE_U32;

        #pragma unroll
        for (int ks = 0; ks < 2; ks++) {       // k0 = 16*ks ; u32 col kk = 8*ks
            const int kk = ks * 8;
            uint32_t ah[4][4], al[4][4], bh[4][2], bl[4][2];
            #pragma unroll
            for (int mt = 0; mt < 4; mt++) {
                const int r = wm0 + mt * 16 + g;
                const int i0 = r * SROW + kk + t;
                const int i1 = (r + 8) * SROW + kk + t;
                ah[mt][0] = Ah[i0];     ah[mt][1] = Ah[i1];
                ah[mt][2] = Ah[i0 + 4]; ah[mt][3] = Ah[i1 + 4];
                al[mt][0] = Al[i0];     al[mt][1] = Al[i1];
                al[mt][2] = Al[i0 + 4]; al[mt][3] = Al[i1 + 4];
            }
            #pragma unroll
            for (int nt = 0; nt < 4; nt++) {
                const int c = wn0 + nt * 8 + g;
                const int i0 = c * SROW + kk + t;
                bh[nt][0] = Bh[i0]; bh[nt][1] = Bh[i0 + 4];
                bl[nt][0] = Bl[i0]; bl[nt][1] = Bl[i0 + 4];
            }
            // term order outermost: consecutive MMAs hit independent accumulators
            #pragma unroll
            for (int mt = 0; mt < 4; mt++)
                #pragma unroll
                for (int nt = 0; nt < 4; nt++) mma_bf16(acc[mt][nt], ah[mt], bh[nt]);
            #pragma unroll
            for (int mt = 0; mt < 4; mt++)
                #pragma unroll
                for (int nt = 0; nt < 4; nt++) mma_bf16(acc[mt][nt], ah[mt], bl[nt]);
            #pragma unroll
            for (int mt = 0; mt < 4; mt++)
                #pragma unroll
                for (int nt = 0; nt < 4; nt++) mma_bf16(acc[mt][nt], al[mt], bh[nt]);
        }
        if (kt + 1 < KT) asm volatile("cp.async.wait_group 0;");
        __syncthreads();
        buf ^= 1;
    }

    // epilogue
    #pragma unroll
    for (int mt = 0; mt < 4; mt++) {
        const int r0 = bm + wm0 + mt * 16 + g;
        float rs0 = 0.f, rs1 = 0.f;
        #pragma unroll
        for (int nt = 0; nt < 4; nt++) {
            const int c = bn + wn0 + nt * 8 + 2 * t;
            float c0 = acc[mt][nt][0], c1 = acc[mt][nt][1];
            float c2 = acc[mt][nt][2], c3 = acc[mt][nt][3];
            if (BIAS) {
                float bb0 = bias[c], bb1 = bias[c + 1];
                c0 += bb0; c1 += bb1; c2 += bb0; c3 += bb1;
            }
            if (OUTSPLIT) {
                uint32_t h01, l01, h23, l23;
                split2(c0, c1, h01, l01);
                split2(c2, c3, h23, l23);
                const size_t p0 = (size_t)r0 * (Ndim >> 1) + (c >> 1);
                const size_t p1 = (size_t)(r0 + 8) * (Ndim >> 1) + (c >> 1);
                ((uint32_t*)Chi)[p0] = h01; ((uint32_t*)Clo)[p0] = l01;
                ((uint32_t*)Chi)[p1] = h23; ((uint32_t*)Clo)[p1] = l23;
            } else {
                *(float2*)(C + (size_t)r0 * Ndim + c)       = make_float2(c0, c1);
                *(float2*)(C + (size_t)(r0 + 8) * Ndim + c) = make_float2(c2, c3);
            }
            if (ROWSUM) { rs0 += c0 + c1; rs1 += c2 + c3; }
        }
        if (ROWSUM) {
            rs0 += __shfl_xor_sync(0xffffffffu, rs0, 1);
            rs0 += __shfl_xor_sync(0xffffffffu, rs0, 2);
            rs1 += __shfl_xor_sync(0xffffffffu, rs1, 1);
            rs1 += __shfl_xor_sync(0xffffffffu, rs1, 2);
            if (t == 0) {
                atomicAdd(&rowsum[r0],     rs0);
                atomicAdd(&rowsum[r0 + 8], rs1);
            }
        }
    }
}

__global__ void zero_kernel(float* p, int n) {
    int i = blockIdx.x * blockDim.x + threadIdx.x;
    if (i < n) p[i] = 0.f;
}

__global__ void dinv_kernel(float* p, int n) {
    int i = blockIdx.x * blockDim.x + threadIdx.x;
    if (i < n) {
        float s = p[i];
        s = s > 1.f ? s : 1.f;
        p[i] = rsqrtf(s);
    }
}

__global__ void scale_kernel(const float* __restrict__ attn,
                             const float* __restrict__ dinv,
                             float* __restrict__ out,
                             int N, size_t total4)
{
    size_t i = (size_t)blockIdx.x * blockDim.x + threadIdx.x;
    if (i >= total4) return;
    size_t e = i * 4;
    size_t row = e / N;
    int j = (int)(e - row * N);
    float4 a = ((const float4*)attn)[i];
    float di = dinv[row];
    const float4 dj = *(const float4*)(dinv + (row / N) * N + j);
    float4 o;
    o.x = a.x * di * dj.x;
    o.y = a.y * di * dj.y;
    o.z = a.z * di * dj.z;
    o.w = a.w * di * dj.w;
    ((float4*)out)[i] = o;
}

extern "C" void kernel_launch(void* const* d_in, const int* in_sizes, int n_in,
                              void* d_out, int out_size)
{
    const float* q  = (const float*)d_in[0];
    const float* W1 = (const float*)d_in[3];
    const float* b1 = (const float*)d_in[4];
    (void)in_sizes; (void)n_in;

    const int B = cB, N = cN, D = cD;
    const size_t BNN = (size_t)B * N * N;

    __nv_bfloat16 *qh, *ql, *wh, *wl, *qoh, *qol;
    float *rowsum, *attn_scratch;
    cudaGetSymbolAddress((void**)&qh, g_q_hi);
    cudaGetSymbolAddress((void**)&ql, g_q_lo);
    cudaGetSymbolAddress((void**)&wh, g_w_hi);
    cudaGetSymbolAddress((void**)&wl, g_w_lo);
    cudaGetSymbolAddress((void**)&qoh, g_qo_hi);
    cudaGetSymbolAddress((void**)&qol, g_qo_lo);
    cudaGetSymbolAddress((void**)&rowsum, g_rowsum);
    cudaGetSymbolAddress((void**)&attn_scratch, g_attn);

    float* outp  = (float*)d_out;
    float* attnp = ((size_t)out_size >= 2 * BNN) ? (outp + BNN) : attn_scratch;

    const int smem = 2 * 4 * PLANE_U32 * (int)sizeof(uint32_t);   // 81920 B
    cudaFuncSetAttribute((const void*)gemm_bf16split<true, true, false>,
                         cudaFuncAttributeMaxDynamicSharedMemorySize, smem);
    cudaFuncSetAttribute((const void*)gemm_bf16split<false, false, true>,
                         cudaFuncAttributeMaxDynamicSharedMemorySize, smem);

    // 0) pre-split inputs into bf16 hi/lo planes
    {
        size_t qn2 = (size_t)B * N * D / 2;
        split_planes_kernel<<<(unsigned)((qn2 + 255) / 256), 256>>>(q, qh, ql, qn2);
        size_t wn2 = (size_t)D * D / 2;
        split_planes_kernel<<<(unsigned)((wn2 + 255) / 256), 256>>>(W1, wh, wl, wn2);
    }

    // 1) zero rowsum accumulators (re-zeroed on every graph replay)
    zero_kernel<<<(B * N + 255) / 256, 256>>>(rowsum, B * N);

    // 2) GEMM1: q_out = q @ W1^T + b1, emitted directly as bf16 hi/lo planes
    {
        dim3 grid(D / BN, (B * N) / BM, 1);
        gemm_bf16split<true, true, false><<<grid, 256, smem>>>(
            qh, ql, wh, wl, b1,
            nullptr, qoh, qol, nullptr,
            B * N, D, D, 0, 0, 0);
    }

    // 3) GEMM2 per batch: attn = q_out @ q_out^T (f32 out), fused row sums
    {
        dim3 grid(N / BN, N / BM, B);
        gemm_bf16split<false, false, true><<<grid, 256, smem>>>(
            qoh, qol, qoh, qol, nullptr,
            attnp, nullptr, nullptr, rowsum,
            N, N, D,
            (size_t)N * D, (size_t)N * D, (size_t)N * N);
    }

    // 4) dinv = rsqrt(max(rowsum, 1))
    dinv_kernel<<<(B * N + 255) / 256, 256>>>(rowsum, B * N);

    // 5) out = dinv * attn * dinv
    {
        size_t total4 = BNN / 4;
        scale_kernel<<<(unsigned)((total4 + 255) / 256), 256>>>(attnp, rowsum, outp, N, total4);
    }
}

// round 16
// speedup vs baseline: 2.4087x; 1.3828x over previous
#include <cuda_runtime.h>
#include <cuda_bf16.h>
#include <cstdint>
#include <cstddef>

// ---------------------------------------------------------------------------
// WeightedScaledDotProductAttention (B=8, N=2048, D=1024)
//   q_out = q @ W1^T + b1 ; attn = q_out @ q_out^T (per batch)
//   dinv = rsqrt(max(rowsum(attn),1)); out = dinv*attn*dinv
// returns (out, attn) -> d_out = [out | attn]
//
// bf16 hi/lo split GEMMs (3x m16n8k16: hh+hl+lh), pre-split bf16 planes.
// ldmatrix fragment loads (48 LDS -> 12 LDSM per ks) + symmetric GEMM2
// (compute upper-tri blocks only, mirror via smem transpose, colsum->rowsum).
// ---------------------------------------------------------------------------

#define BM 128
#define BN 128
#define BK 32
#define SROW 20                 // smem row stride in u32 (40 bf16); perm banks
#define PLANE_U32 (BM * SROW)   // 2560 u32 per plane per buffer

static const int cB = 8, cN = 2048, cD = 1024;

__device__ __nv_bfloat16 g_q_hi[(size_t)8 * 2048 * 1024];
__device__ __nv_bfloat16 g_q_lo[(size_t)8 * 2048 * 1024];
__device__ __nv_bfloat16 g_w_hi[(size_t)1024 * 1024];
__device__ __nv_bfloat16 g_w_lo[(size_t)1024 * 1024];
__device__ __nv_bfloat16 g_qo_hi[(size_t)8 * 2048 * 1024];
__device__ __nv_bfloat16 g_qo_lo[(size_t)8 * 2048 * 1024];
__device__ float g_attn[(size_t)8 * 2048 * 2048];
__device__ float g_rowsum[8 * 2048];

__device__ __forceinline__ uint32_t bits2(__nv_bfloat162 h) {
    uint32_t u; *reinterpret_cast<__nv_bfloat162*>(&u) = h; return u;
}

__device__ __forceinline__ void split2(float a, float b, uint32_t& hi, uint32_t& lo) {
    __nv_bfloat162 h = __floats2bfloat162_rn(a, b);
    float ra = a - __bfloat162float(h.x);
    float rb = b - __bfloat162float(h.y);
    hi = bits2(h);
    lo = bits2(__floats2bfloat162_rn(ra, rb));
}

__device__ __forceinline__ void mma_bf16(float c[4], const uint32_t a[4], const uint32_t b[2]) {
    asm volatile(
        "mma.sync.aligned.m16n8k16.row.col.f32.bf16.bf16.f32 "
        "{%0,%1,%2,%3}, {%4,%5,%6,%7}, {%8,%9}, {%0,%1,%2,%3};"
        : "+f"(c[0]), "+f"(c[1]), "+f"(c[2]), "+f"(c[3])
        : "r"(a[0]), "r"(a[1]), "r"(a[2]), "r"(a[3]), "r"(b[0]), "r"(b[1]));
}

__device__ __forceinline__ void ldsm4(uint32_t d[4], uint32_t byte_addr) {
    asm volatile("ldmatrix.sync.aligned.m8n8.x4.shared.b16 {%0,%1,%2,%3}, [%4];"
        : "=r"(d[0]), "=r"(d[1]), "=r"(d[2]), "=r"(d[3]) : "r"(byte_addr));
}

__device__ __forceinline__ void cpasync16(void* smem_dst, const void* gmem_src) {
    uint32_t s = (uint32_t)__cvta_generic_to_shared(smem_dst);
    asm volatile("cp.async.cg.shared.global [%0], [%1], 16;" :: "r"(s), "l"(gmem_src));
}

__global__ void split_planes_kernel(const float* __restrict__ x,
                                    __nv_bfloat16* __restrict__ hi,
                                    __nv_bfloat16* __restrict__ lo, size_t npairs)
{
    size_t i = (size_t)blockIdx.x * blockDim.x + threadIdx.x;
    if (i >= npairs) return;
    float2 v = ((const float2*)x)[i];
    uint32_t h, l;
    split2(v.x, v.y, h, l);
    ((uint32_t*)hi)[i] = h;
    ((uint32_t*)lo)[i] = l;
}

// C[M,Ndim] = (Ahi+Alo)[M,K] * (Bhi+Blo)[Ndim,K]^T via hh+hl+lh, fp32 acc.
// OUTSPLIT: emit bf16 hi/lo planes (+bias). ROWSUM: fused rowsum atomics.
// SYM: A==B per batch; blockIdx.x enumerates upper-tri (bi<=bj) blocks;
//      off-diagonal blocks also mirror-store C^T and add column sums.
template <bool OUTSPLIT, bool BIAS, bool ROWSUM, bool SYM>
__global__ __launch_bounds__(256, 1)
void gemm_bf16split(const __nv_bfloat16* __restrict__ Ahi, const __nv_bfloat16* __restrict__ Alo,
                    const __nv_bfloat16* __restrict__ Bhi, const __nv_bfloat16* __restrict__ Blo,
                    const float* __restrict__ bias,
                    float* __restrict__ Cf,
                    __nv_bfloat16* __restrict__ Chi, __nv_bfloat16* __restrict__ Clo,
                    float* __restrict__ rowsumg,
                    int M, int Ndim, int K,
                    size_t sA, size_t sB, size_t sC)
{
    extern __shared__ uint32_t sm32[];   // [2 buf][4 planes][BM][SROW]

    const int z = blockIdx.z;
    const __nv_bfloat16* pA[2] = { Ahi + (size_t)z * sA, Alo + (size_t)z * sA };
    const __nv_bfloat16* pB[2] = { Bhi + (size_t)z * sB, Blo + (size_t)z * sB };
    float* C = OUTSPLIT ? nullptr : (Cf + (size_t)z * sC);
    float* rowsum = ROWSUM ? (rowsumg + (size_t)z * M) : nullptr;

    int bm, bn;
    if (SYM) {
        const int NB = Ndim / BN;            // 16
        int rem = blockIdx.x, bi = 0;
        #pragma unroll 1
        while (rem >= NB - bi) { rem -= NB - bi; bi++; }
        bm = bi * BM;
        bn = (bi + rem) * BN;
    } else {
        bm = blockIdx.y * BM;
        bn = blockIdx.x * BN;
    }

    const int tid  = threadIdx.x;
    const int lane = tid & 31;
    const int warp = tid >> 5;
    const int g = lane >> 2;
    const int t = lane & 3;
    const int wm0 = (warp >> 2) * 64;   // warp grid 2x4, warp tile 64x32
    const int wn0 = (warp & 3) * 32;

    // ldmatrix per-lane selectors
    const uint32_t smemB = (uint32_t)__cvta_generic_to_shared(sm32);
    const int aRow = wm0 + (lane & 15);
    const int aCol = (lane >> 4) * 4;                       // u32 offset 0/4
    const int bRow = wn0 + (lane & 7) + ((lane & 16) ? 8 : 0);
    const int bCol = ((lane >> 3) & 1) * 4;

    float acc[4][4][4];
    #pragma unroll
    for (int i = 0; i < 4; i++)
        #pragma unroll
        for (int j = 0; j < 4; j++)
            #pragma unroll
            for (int r = 0; r < 4; r++) acc[i][j][r] = 0.f;

    const int KT = K / BK;

    auto load_tile = [&](int kt, int buf) {
        uint32_t* base = sm32 + buf * 4 * PLANE_U32;
        #pragma unroll
        for (int p = 0; p < 4; p++) {
            const __nv_bfloat16* src = (p < 2) ? (pA[p] + (size_t)bm * K + kt * BK)
                                               : (pB[p - 2] + (size_t)bn * K + kt * BK);
            uint32_t* dst = base + p * PLANE_U32;
            #pragma unroll
            for (int j = 0; j < 2; j++) {
                int chunk = tid + j * 256;
                int r  = chunk >> 2;
                int ch = chunk & 3;
                cpasync16(dst + r * SROW + ch * 4, src + (size_t)r * K + ch * 8);
            }
        }
        asm volatile("cp.async.commit_group;");
    };

    load_tile(0, 0);
    asm volatile("cp.async.wait_group 0;");
    __syncthreads();

    int buf = 0;
    for (int kt = 0; kt < KT; kt++) {
        if (kt + 1 < KT) load_tile(kt + 1, buf ^ 1);
        const uint32_t pAh = (buf * 4 + 0) * PLANE_U32;
        const uint32_t pAl = (buf * 4 + 1) * PLANE_U32;
        const uint32_t pBh = (buf * 4 + 2) * PLANE_U32;
        const uint32_t pBl = (buf * 4 + 3) * PLANE_U32;

        #pragma unroll
        for (int ks = 0; ks < 2; ks++) {
            const int kk = ks * 8;
            uint32_t ah[4][4], al[4][4], bh[4][2], bl[4][2];
            const uint32_t aIdx = (uint32_t)(aRow * SROW + kk + aCol);
            const uint32_t bIdx = (uint32_t)(bRow * SROW + kk + bCol);
            #pragma unroll
            for (int mt = 0; mt < 4; mt++) {
                const uint32_t off = aIdx + mt * 16 * SROW;
                ldsm4(ah[mt], smemB + (pAh + off) * 4);
                ldsm4(al[mt], smemB + (pAl + off) * 4);
            }
            #pragma unroll
            for (int np = 0; np < 2; np++) {
                const uint32_t off = bIdx + np * 16 * SROW;
                uint32_t d[4];
                ldsm4(d, smemB + (pBh + off) * 4);
                bh[2*np][0] = d[0]; bh[2*np][1] = d[1];
                bh[2*np+1][0] = d[2]; bh[2*np+1][1] = d[3];
                ldsm4(d, smemB + (pBl + off) * 4);
                bl[2*np][0] = d[0]; bl[2*np][1] = d[1];
                bl[2*np+1][0] = d[2]; bl[2*np+1][1] = d[3];
            }
            #pragma unroll
            for (int mt = 0; mt < 4; mt++)
                #pragma unroll
                for (int nt = 0; nt < 4; nt++) mma_bf16(acc[mt][nt], ah[mt], bh[nt]);
            #pragma unroll
            for (int mt = 0; mt < 4; mt++)
                #pragma unroll
                for (int nt = 0; nt < 4; nt++) mma_bf16(acc[mt][nt], ah[mt], bl[nt]);
            #pragma unroll
            for (int mt = 0; mt < 4; mt++)
                #pragma unroll
                for (int nt = 0; nt < 4; nt++) mma_bf16(acc[mt][nt], al[mt], bh[nt]);
        }
        if (kt + 1 < KT) asm volatile("cp.async.wait_group 0;");
        __syncthreads();
        buf ^= 1;
    }
    // final __syncthreads above fences all tile reads; smem reusable below

    const bool mirror = SYM && (bm != bn);

    // main store + row sums (rows of block-row bm)
    #pragma unroll
    for (int mt = 0; mt < 4; mt++) {
        const int r0 = bm + wm0 + mt * 16 + g;
        float rs0 = 0.f, rs1 = 0.f;
        #pragma unroll
        for (int nt = 0; nt < 4; nt++) {
            const int c = bn + wn0 + nt * 8 + 2 * t;
            float c0 = acc[mt][nt][0], c1 = acc[mt][nt][1];
            float c2 = acc[mt][nt][2], c3 = acc[mt][nt][3];
            if (BIAS) {
                float bb0 = bias[c], bb1 = bias[c + 1];
                c0 += bb0; c1 += bb1; c2 += bb0; c3 += bb1;
                acc[mt][nt][0] = c0; acc[mt][nt][1] = c1;
                acc[mt][nt][2] = c2; acc[mt][nt][3] = c3;
            }
            if (OUTSPLIT) {
                uint32_t h01, l01, h23, l23;
                split2(c0, c1, h01, l01);
                split2(c2, c3, h23, l23);
                const size_t p0 = (size_t)r0 * (Ndim >> 1) + (c >> 1);
                const size_t p1 = (size_t)(r0 + 8) * (Ndim >> 1) + (c >> 1);
                ((uint32_t*)Chi)[p0] = h01; ((uint32_t*)Clo)[p0] = l01;
                ((uint32_t*)Chi)[p1] = h23; ((uint32_t*)Clo)[p1] = l23;
            } else {
                *(float2*)(C + (size_t)r0 * Ndim + c)       = make_float2(c0, c1);
                *(float2*)(C + (size_t)(r0 + 8) * Ndim + c) = make_float2(c2, c3);
            }
            if (ROWSUM) { rs0 += c0 + c1; rs1 += c2 + c3; }
        }
        if (ROWSUM) {
            rs0 += __shfl_xor_sync(0xffffffffu, rs0, 1);
            rs0 += __shfl_xor_sync(0xffffffffu, rs0, 2);
            rs1 += __shfl_xor_sync(0xffffffffu, rs1, 1);
            rs1 += __shfl_xor_sync(0xffffffffu, rs1, 2);
            if (t == 0) {
                atomicAdd(&rowsum[r0],     rs0);
                atomicAdd(&rowsum[r0 + 8], rs1);
            }
        }
    }

    if (mirror) {
        // column sums -> row sums of mirrored block-row (rows bn..bn+127)
        if (ROWSUM) {
            float cs[4][2];
            #pragma unroll
            for (int nt = 0; nt < 4; nt++) {
                float s0 = 0.f, s1 = 0.f;
                #pragma unroll
                for (int mt = 0; mt < 4; mt++) {
                    s0 += acc[mt][nt][0] + acc[mt][nt][2];
                    s1 += acc[mt][nt][1] + acc[mt][nt][3];
                }
                cs[nt][0] = s0; cs[nt][1] = s1;
            }
            #pragma unroll
            for (int nt = 0; nt < 4; nt++) {
                #pragma unroll
                for (int s = 4; s <= 16; s <<= 1) {
                    cs[nt][0] += __shfl_xor_sync(0xffffffffu, cs[nt][0], s);
                    cs[nt][1] += __shfl_xor_sync(0xffffffffu, cs[nt][1], s);
                }
            }
            if (g == 0) {
                #pragma unroll
                for (int nt = 0; nt < 4; nt++) {
                    atomicAdd(&rowsum[bn + wn0 + nt * 8 + 2 * t],     cs[nt][0]);
                    atomicAdd(&rowsum[bn + wn0 + nt * 8 + 2 * t + 1], cs[nt][1]);
                }
            }
        }
        // transpose-stage the block in smem, then coalesced mirror store
        float* st = (float*)sm32;          // 128 x 132 f32 = 67584 B <= 81920 B
        #pragma unroll
        for (int mt = 0; mt < 4; mt++) {
            const int rl = wm0 + mt * 16 + g;
            #pragma unroll
            for (int nt = 0; nt < 4; nt++) {
                const int cl = wn0 + nt * 8 + 2 * t;
                st[cl * 132 + rl]           = acc[mt][nt][0];
                st[(cl + 1) * 132 + rl]     = acc[mt][nt][1];
                st[cl * 132 + rl + 8]       = acc[mt][nt][2];
                st[(cl + 1) * 132 + rl + 8] = acc[mt][nt][3];
            }
        }
        __syncthreads();
        #pragma unroll 1
        for (int rr = 0; rr < 16; rr++) {
            const int cl = warp * 16 + rr;          // original col = mirrored row
            const float* src = st + cl * 132 + 4 * lane;
            float4 v = make_float4(src[0], src[1], src[2], src[3]);
            *(float4*)(C + (size_t)(bn + cl) * Ndim + bm + 4 * lane) = v;
        }
    }
}

__global__ void zero_kernel(float* p, int n) {
    int i = blockIdx.x * blockDim.x + threadIdx.x;
    if (i < n) p[i] = 0.f;
}

__global__ void dinv_kernel(float* p, int n) {
    int i = blockIdx.x * blockDim.x + threadIdx.x;
    if (i < n) {
        float s = p[i];
        s = s > 1.f ? s : 1.f;
        p[i] = rsqrtf(s);
    }
}

__global__ void scale_kernel(const float* __restrict__ attn,
                             const float* __restrict__ dinv,
                             float* __restrict__ out,
                             int N, size_t total4)
{
    size_t i = (size_t)blockIdx.x * blockDim.x + threadIdx.x;
    if (i >= total4) return;
    size_t e = i * 4;
    size_t row = e / N;
    int j = (int)(e - row * N);
    float4 a = ((const float4*)attn)[i];
    float di = dinv[row];
    const float4 dj = *(const float4*)(dinv + (row / N) * N + j);
    float4 o;
    o.x = a.x * di * dj.x;
    o.y = a.y * di * dj.y;
    o.z = a.z * di * dj.z;
    o.w = a.w * di * dj.w;
    ((float4*)out)[i] = o;
}

extern "C" void kernel_launch(void* const* d_in, const int* in_sizes, int n_in,
                              void* d_out, int out_size)
{
    const float* q  = (const float*)d_in[0];
    const float* W1 = (const float*)d_in[3];
    const float* b1 = (const float*)d_in[4];
    (void)in_sizes; (void)n_in;

    const int B = cB, N = cN, D = cD;
    const size_t BNN = (size_t)B * N * N;

    __nv_bfloat16 *qh, *ql, *wh, *wl, *qoh, *qol;
    float *rowsum, *attn_scratch;
    cudaGetSymbolAddress((void**)&qh, g_q_hi);
    cudaGetSymbolAddress((void**)&ql, g_q_lo);
    cudaGetSymbolAddress((void**)&wh, g_w_hi);
    cudaGetSymbolAddress((void**)&wl, g_w_lo);
    cudaGetSymbolAddress((void**)&qoh, g_qo_hi);
    cudaGetSymbolAddress((void**)&qol, g_qo_lo);
    cudaGetSymbolAddress((void**)&rowsum, g_rowsum);
    cudaGetSymbolAddress((void**)&attn_scratch, g_attn);

    float* outp  = (float*)d_out;
    float* attnp = ((size_t)out_size >= 2 * BNN) ? (outp + BNN) : attn_scratch;

    const int smem = 2 * 4 * PLANE_U32 * (int)sizeof(uint32_t);   // 81920 B
    cudaFuncSetAttribute((const void*)gemm_bf16split<true, true, false, false>,
                         cudaFuncAttributeMaxDynamicSharedMemorySize, smem);
    cudaFuncSetAttribute((const void*)gemm_bf16split<false, false, true, true>,
                         cudaFuncAttributeMaxDynamicSharedMemorySize, smem);

    // 0) pre-split inputs into bf16 hi/lo planes
    {
        size_t qn2 = (size_t)B * N * D / 2;
        split_planes_kernel<<<(unsigned)((qn2 + 255) / 256), 256>>>(q, qh, ql, qn2);
        size_t wn2 = (size_t)D * D / 2;
        split_planes_kernel<<<(unsigned)((wn2 + 255) / 256), 256>>>(W1, wh, wl, wn2);
    }

    // 1) zero rowsum accumulators (re-zeroed on every graph replay)
    zero_kernel<<<(B * N + 255) / 256, 256>>>(rowsum, B * N);

    // 2) GEMM1: q_out = q @ W1^T + b1 -> bf16 hi/lo planes
    {
        dim3 grid(D / BN, (B * N) / BM, 1);
        gemm_bf16split<true, true, false, false><<<grid, 256, smem>>>(
            qh, ql, wh, wl, b1,
            nullptr, qoh, qol, nullptr,
            B * N, D, D, 0, 0, 0);
    }

    // 3) GEMM2 per batch, symmetric: upper-tri blocks only (136 of 256)
    {
        const int NB = N / BN;                      // 16
        dim3 grid(NB * (NB + 1) / 2, 1, B);         // 136 x 1 x 8
        gemm_bf16split<false, false, true, true><<<grid, 256, smem>>>(
            qoh, qol, qoh, qol, nullptr,
            attnp, nullptr, nullptr, rowsum,
            N, N, D,
            (size_t)N * D, (size_t)N * D, (size_t)N * N);
    }

    // 4) dinv = rsqrt(max(rowsum, 1))
    dinv_kernel<<<(B * N + 255) / 256, 256>>>(rowsum, B * N);

    // 5) out = dinv * attn * dinv
    {
        size_t total4 = BNN / 4;
        scale_kernel<<<(unsigned)((total4 + 255) / 256), 256>>>(attnp, rowsum, outp, N, total4);
    }
}